// round 15
// baseline (speedup 1.0000x reference)
#include <cuda_runtime.h>
#include <cuda_fp16.h>
#include <math.h>
#include <stdint.h>

typedef __half hf;

// Problem constants
#define B_   2
#define S_   2048
#define H_   2048
#define NH_  16
#define DN_  128
#define DR_  64
#define DV_  128
#define QR_  1536
#define KVR_ 512
#define QD_  192
#define TOK  (B_*S_)          // 4096
#define ZBH  (B_*NH_)         // 32
#define W1N  (QR_ + KVR_ + DR_)   // 2112

#define EXP_OFF 5.0f

// ---------------------------------------------------------------------------
// Scratch (device globals)
// ---------------------------------------------------------------------------
__device__ hf  g_hid_h [TOK*2048];
__device__ hf  g_w1    [W1N*2048];                       // [N,K] merged qdw|kvdw
__device__ hf  g_qup_h [3072*1536];
__device__ hf  g_kvupw_h[4096*512];
__device__ hf  g_outw_h[2048*2048];
__device__ float g_kvq [TOK*W1N];                        // merged qlat|kv (fp32)
__device__ hf  g_qlat_h[TOK*QR_];
__device__ hf  g_kvlat_h[TOK*KVR_];
__device__ hf  g_kvup_h[TOK*4096];                       // fp16 kvup (v region used)
__device__ hf  g_qs_h  [(size_t)ZBH*S_*QD_];
__device__ hf  g_ks_h  [(size_t)ZBH*S_*QD_];
__device__ hf  g_vt_h  [(size_t)ZBH*DV_*S_];
__device__ hf  g_at_h  [(size_t)ZBH*S_*S_];              // fp16 unnormalized exp(p)
__device__ float g_invs[(size_t)ZBH*S_];
__device__ hf  g_ao_h  [TOK*2048];

// ---------------------------------------------------------------------------
// Portable PTX helpers
// ---------------------------------------------------------------------------
__device__ __forceinline__ uint32_t smem_u32(const void* p) {
    uint32_t a;
    asm("{ .reg .u64 t; cvta.to.shared.u64 t, %1; cvt.u32.u64 %0, t; }"
        : "=r"(a) : "l"(p));
    return a;
}

__device__ __forceinline__ void ldsm4(uint32_t* r, uint32_t addr) {
    asm volatile("ldmatrix.sync.aligned.m8n8.x4.shared.b16 {%0,%1,%2,%3}, [%4];"
        : "=r"(r[0]), "=r"(r[1]), "=r"(r[2]), "=r"(r[3]) : "r"(addr));
}

__device__ __forceinline__ void mma16816(float* c, const uint32_t* a, const uint32_t* b) {
    asm volatile(
        "mma.sync.aligned.m16n8k16.row.col.f32.f16.f16.f32 "
        "{%0,%1,%2,%3}, {%4,%5,%6,%7}, {%8,%9}, {%0,%1,%2,%3};"
        : "+f"(c[0]), "+f"(c[1]), "+f"(c[2]), "+f"(c[3])
        : "r"(a[0]), "r"(a[1]), "r"(a[2]), "r"(a[3]), "r"(b[0]), "r"(b[1]));
}

__device__ __forceinline__ void cp16(uint32_t dst, const void* src, bool v) {
    int sz = v ? 16 : 0;
    asm volatile("cp.async.cg.shared.global [%0], [%1], 16, %2;"
                 :: "r"(dst), "l"(src), "r"(sz) : "memory");
}

template<int W> __device__ __forceinline__ void cp_wait() {
    asm volatile("cp.async.wait_group %0;" :: "n"(W) : "memory");
}

__device__ __forceinline__ void rope_cs(int pos, int f, float& c, float& s)
{
    float invf = (float)exp(-(double)f * 9.210340371976184 / 32.0);
    float arg = (float)pos * invf;
    c = cosf(arg); s = sinf(arg);
}

#define LDT      72                    // padded row stride in halves (144 B)

// load one stage: A tile (MT x 64) + B tile (NT x 64)  (P=1 or 2)
template<int NT, int MT, int P>
__device__ __forceinline__ void load_stage(
    uint32_t sbase, int kc, int tid, int m0, int n0, int N,
    const hf* __restrict__ Ah, const hf* __restrict__ Al, int lda,
    const hf* __restrict__ Bh, int ldb)
{
    constexpr int TILE_A = MT * LDT * 2;
    const int ROWS = P * MT + NT;
    const int ITERS = ROWS / 32;
#pragma unroll
    for (int it = 0; it < ITERS; it++) {
        int idx = tid + it * 256;
        int r = idx >> 3, sg = idx & 7;
        if (r < MT) {
            cp16(sbase + (uint32_t)(r * LDT + sg * 8) * 2,
                 Ah + (long)(m0 + r) * lda + kc + sg * 8, true);
        } else if (P == 2 && r < 2 * MT) {
            int rr = r - MT;
            cp16(sbase + TILE_A + (uint32_t)(rr * LDT + sg * 8) * 2,
                 Al + (long)(m0 + rr) * lda + kc + sg * 8, true);
        } else {
            int rr = r - P * MT;
            bool bv = (n0 + rr) < N;
            cp16(sbase + P * TILE_A + (uint32_t)(rr * LDT + sg * 8) * 2,
                 Bh + (long)(bv ? n0 + rr : 0) * ldb + kc + sg * 8, bv);
        }
    }
    asm volatile("cp.async.commit_group;" ::: "memory");
}

// ---------------------------------------------------------------------------
// Main templated GEMM. EMODE 0: fp32; 1: fp16*rowscale; 2: fp16 exp.
// ---------------------------------------------------------------------------
template<int NT, int MT, int P, int EMODE>
__global__ __launch_bounds__(256, 1)
void gemm_t(const hf* __restrict__ Ah, const hf* __restrict__ Al,
            long sA, int lda,
            const hf* __restrict__ Bh, long sB, int ldb,
            void* __restrict__ C0, long sCb, long sCh, int ldc,
            const float* __restrict__ rowscale,
            int N, int K, float alpha)
{
    constexpr int MW = MT / 64;
    constexpr int NW = 8 / MW;
    constexpr int WN = NT / NW;
    constexpr int NI = WN / 8;
    constexpr int NG = WN / 16;
    constexpr int TILE_A = MT * LDT * 2;
    constexpr int STAGE_B = P * TILE_A + NT * LDT * 2;

    extern __shared__ char smem[];
    const uint32_t smb = smem_u32(smem);

    const int tid  = threadIdx.x;
    const int lane = tid & 31;
    const int wid  = tid >> 5;
    const int wm   = wid / NW;
    const int wn   = wid % NW;
    const int z    = blockIdx.z;
    const int m0   = blockIdx.y * MT;
    const int n0   = blockIdx.x * NT;

    Ah += (long)z * sA;  if (P == 2) Al += (long)z * sA;
    Bh += (long)z * sB;
    const long coff = (long)(z >> 4) * sCb + (long)(z & 15) * sCh;

    float acc[4][NI][4];
#pragma unroll
    for (int mi = 0; mi < 4; mi++)
#pragma unroll
        for (int ni = 0; ni < NI; ni++)
#pragma unroll
            for (int j = 0; j < 4; j++) acc[mi][ni][j] = 0.f;

    const int NC = K / 64;

    load_stage<NT, MT, P>(smb, 0, tid, m0, n0, N, Ah, Al, lda, Bh, ldb);
    load_stage<NT, MT, P>(smb + STAGE_B, 64, tid, m0, n0, N, Ah, Al, lda, Bh, ldb);

    const int a_r = (lane & 15);
    const int a_k = (lane >> 4) << 3;
    const int b_n = ((lane >> 4) << 3) + (lane & 7);
    const int b_k = ((lane >> 3) & 1) << 3;

    int stage = 0;
    for (int c = 0; c < NC; c++) {
        if (c + 2 < NC) {
            int ns = stage + 2; if (ns >= 3) ns -= 3;
            load_stage<NT, MT, P>(smb + ns * STAGE_B, (c + 2) * 64, tid, m0, n0, N,
                                  Ah, Al, lda, Bh, ldb);
            cp_wait<2>();
        } else if (c + 1 < NC) {
            cp_wait<1>();
        } else {
            cp_wait<0>();
        }
        __syncthreads();

        const uint32_t sbase = smb + stage * STAGE_B;

#pragma unroll
        for (int ks = 0; ks < 64; ks += 16) {
            uint32_t aH[4][4], aX[P == 2 ? 4 : 1][4], bH[NG][4];
#pragma unroll
            for (int mi = 0; mi < 4; mi++) {
                uint32_t off = (uint32_t)((wm * 64 + mi * 16 + a_r) * LDT + ks + a_k) * 2;
                ldsm4(aH[mi], sbase + off);
                if (P == 2) ldsm4(aX[mi], sbase + TILE_A + off);
            }
#pragma unroll
            for (int g = 0; g < NG; g++) {
                uint32_t off = (uint32_t)((wn * WN + g * 16 + b_n) * LDT + ks + b_k) * 2;
                ldsm4(bH[g], sbase + P * TILE_A + off);
            }
#pragma unroll
            for (int p = 0; p < P; p++) {
#pragma unroll
                for (int mi = 0; mi < 4; mi++)
#pragma unroll
                    for (int ni = 0; ni < NI; ni++)
                        mma16816(acc[mi][ni],
                                 (p == 1) ? aX[mi] : aH[mi],
                                 &bH[ni >> 1][(ni & 1) * 2]);
            }
        }
        __syncthreads();
        stage++; if (stage == 3) stage = 0;
    }

    // epilogue
#pragma unroll
    for (int mi = 0; mi < 4; mi++) {
        int r0 = m0 + wm * 64 + mi * 16 + (lane >> 2);
        float is0 = 1.f, is1 = 1.f;
        if (EMODE == 1) {
            is0 = rowscale[(long)z * S_ + r0];
            is1 = rowscale[(long)z * S_ + r0 + 8];
        }
#pragma unroll
        for (int ni = 0; ni < NI; ni++) {
            int col = n0 + wn * WN + ni * 8 + (lane & 3) * 2;
            if (col >= N) continue;
            float v0 = alpha * acc[mi][ni][0], v1 = alpha * acc[mi][ni][1];
            float v2 = alpha * acc[mi][ni][2], v3 = alpha * acc[mi][ni][3];
            if (EMODE == 2) {
                const float L2E = 1.44269504f, OF2 = EXP_OFF * 1.44269504f;
                v0 = exp2f(v0 * L2E - OF2);
                v1 = exp2f(v1 * L2E - OF2);
                v2 = exp2f(v2 * L2E - OF2);
                v3 = exp2f(v3 * L2E - OF2);
            } else if (EMODE == 1) {
                v0 *= is0; v1 *= is0; v2 *= is1; v3 *= is1;
            }
            if (EMODE != 0) {
                hf* C = (hf*)C0 + coff;
                *(__half2*)&C[(long)r0 * ldc + col] =
                    __halves2half2(__float2half(v0), __float2half(v1));
                *(__half2*)&C[(long)(r0 + 8) * ldc + col] =
                    __halves2half2(__float2half(v2), __float2half(v3));
            } else {
                float* C = (float*)C0 + coff;
                *(float2*)&C[(long)r0 * ldc + col]       = make_float2(v0, v1);
                *(float2*)&C[(long)(r0 + 8) * ldc + col] = make_float2(v2, v3);
            }
        }
    }
}

// ---------------------------------------------------------------------------
// gemm_pair: qup + kvup in ONE launch, fused epilogues.
//   GEMM-0 (qup):  applies RoPE + head-permute, writes qs [b,h,s,192] directly.
//   GEMM-1 (kvup): k_nope -> ks [b,h,s,192] directly; v cols -> kvup_h [tok,4096].
//   Both NT=256, MT=128, P=1. Flat 1-D grid; blocks [0,nc0) run GEMM-0.
// ---------------------------------------------------------------------------
__global__ __launch_bounds__(256, 1)
void gemm_pair(const hf* __restrict__ A0, const hf* __restrict__ B0, int k0,
               int nx0, int nc0,
               const hf* __restrict__ A1, const hf* __restrict__ B1, int k1,
               int nx1,
               const int* __restrict__ pos,
               hf* __restrict__ qs, hf* __restrict__ ks, hf* __restrict__ kvup)
{
    constexpr int NT = 256, MT = 128;
    constexpr int STAGE_B = MT * LDT * 2 + NT * LDT * 2;

    extern __shared__ char smem[];
    const uint32_t smb = smem_u32(smem);

    const int tid  = threadIdx.x;
    const int lane = tid & 31;
    const int wid  = tid >> 5;
    const int wm   = wid / 4;
    const int wn   = wid % 4;

    const bool g0 = (blockIdx.x < nc0);
    const hf* Ah; const hf* Bh;
    int lda, K, bx, by;
    {
        int id = blockIdx.x;
        if (g0) { Ah = A0; Bh = B0; lda = k0; K = k0; bx = id % nx0; by = id / nx0; }
        else    { id -= nc0;
                  Ah = A1; Bh = B1; lda = k1; K = k1; bx = id % nx1; by = id / nx1; }
    }
    const int m0 = by * MT;
    const int n0 = bx * NT;

    float acc[4][8][4];
#pragma unroll
    for (int mi = 0; mi < 4; mi++)
#pragma unroll
        for (int ni = 0; ni < 8; ni++)
#pragma unroll
            for (int j = 0; j < 4; j++) acc[mi][ni][j] = 0.f;

    const int NC = K / 64;

    load_stage<NT, MT, 1>(smb, 0, tid, m0, n0, 1 << 30, Ah, nullptr, lda, Bh, lda);
    load_stage<NT, MT, 1>(smb + STAGE_B, 64, tid, m0, n0, 1 << 30, Ah, nullptr, lda, Bh, lda);

    const int a_r = (lane & 15);
    const int a_k = (lane >> 4) << 3;
    const int b_n = ((lane >> 4) << 3) + (lane & 7);
    const int b_k = ((lane >> 3) & 1) << 3;

    int stage = 0;
    for (int c = 0; c < NC; c++) {
        if (c + 2 < NC) {
            int ns = stage + 2; if (ns >= 3) ns -= 3;
            load_stage<NT, MT, 1>(smb + ns * STAGE_B, (c + 2) * 64, tid, m0, n0, 1 << 30,
                                  Ah, nullptr, lda, Bh, lda);
            cp_wait<2>();
        } else if (c + 1 < NC) {
            cp_wait<1>();
        } else {
            cp_wait<0>();
        }
        __syncthreads();

        const uint32_t sbase = smb + stage * STAGE_B;

#pragma unroll
        for (int ks2 = 0; ks2 < 64; ks2 += 16) {
            uint32_t aH[4][4], bH[4][4];
#pragma unroll
            for (int mi = 0; mi < 4; mi++) {
                uint32_t off = (uint32_t)((wm * 64 + mi * 16 + a_r) * LDT + ks2 + a_k) * 2;
                ldsm4(aH[mi], sbase + off);
            }
#pragma unroll
            for (int g = 0; g < 4; g++) {
                uint32_t off = (uint32_t)((wn * 64 + g * 16 + b_n) * LDT + ks2 + b_k) * 2;
                ldsm4(bH[g], sbase + MT * LDT * 2 + off);
            }
#pragma unroll
            for (int mi = 0; mi < 4; mi++)
#pragma unroll
                for (int ni = 0; ni < 8; ni++)
                    mma16816(acc[mi][ni], aH[mi], &bH[ni >> 1][(ni & 1) * 2]);
        }
        __syncthreads();
        stage++; if (stage == 3) stage = 0;
    }

    // fused epilogues
#pragma unroll
    for (int mi = 0; mi < 4; mi++) {
        int r0 = m0 + wm * 64 + mi * 16 + (lane >> 2);
        int b0 = r0 >> 11, s0 = r0 & 2047;
        int pa = 0, pb = 0;
        if (g0) { pa = pos[s0]; pb = pos[s0 + 8]; }
#pragma unroll
        for (int ni = 0; ni < 8; ni++) {
            int col = n0 + wn * 64 + ni * 8 + (lane & 3) * 2;
            float v0 = acc[mi][ni][0], v1 = acc[mi][ni][1];
            float v2 = acc[mi][ni][2], v3 = acc[mi][ni][3];
            if (g0) {
                // qup: head h = col/192, dim dd = col%192; rope on dd>=128
                int h = col / 192, dd = col - h * 192;
                if (dd >= 128) {
                    int j = dd - 128;
                    const float* pp = acc[mi][ni ^ 4];
                    float sgn = (j < 32) ? -1.f : 1.f;
                    float c0, sn0, c1, sn1, d0, dn0, d1, dn1;
                    rope_cs(pa, j & 31, c0, sn0);
                    rope_cs(pa, (j + 1) & 31, c1, sn1);
                    rope_cs(pb, j & 31, d0, dn0);
                    rope_cs(pb, (j + 1) & 31, d1, dn1);
                    v0 = v0 * c0 + sgn * pp[0] * sn0;
                    v1 = v1 * c1 + sgn * pp[1] * sn1;
                    v2 = v2 * d0 + sgn * pp[2] * dn0;
                    v3 = v3 * d1 + sgn * pp[3] * dn1;
                }
                long o = (((long)(b0 * NH_ + h)) * S_ + s0) * QD_ + dd;
                *(__half2*)&qs[o] =
                    __halves2half2(__float2half(v0), __float2half(v1));
                *(__half2*)&qs[o + 8 * QD_] =
                    __halves2half2(__float2half(v2), __float2half(v3));
            } else {
                // kvup: head h = col/256, dim dd = col%256
                int h = col >> 8, dd = col & 255;
                __half2 w0 = __halves2half2(__float2half(v0), __float2half(v1));
                __half2 w1 = __halves2half2(__float2half(v2), __float2half(v3));
                if (dd < 128) {
                    long o = (((long)(b0 * NH_ + h)) * S_ + s0) * QD_ + dd;
                    *(__half2*)&ks[o]            = w0;
                    *(__half2*)&ks[o + 8 * QD_]  = w1;
                } else {
                    *(__half2*)&kvup[(long)r0 * 4096 + col]       = w0;
                    *(__half2*)&kvup[(long)(r0 + 8) * 4096 + col] = w1;
                }
            }
        }
    }
}

// ---------------------------------------------------------------------------
// Elementwise / conversion kernels
// ---------------------------------------------------------------------------
__global__ void conv_h(const float4* __restrict__ x, hf* __restrict__ h, int n4)
{
    int i = blockIdx.x * 256 + threadIdx.x;
    if (i >= n4) return;
    float4 v = x[i];
    __half2 a = __halves2half2(__float2half(v.x), __float2half(v.y));
    __half2 b = __halves2half2(__float2half(v.z), __float2half(v.w));
    uint2 pk; pk.x = *(uint32_t*)&a; pk.y = *(uint32_t*)&b;
    ((uint2*)h)[i] = pk;
}

// fp32 [R,C] -> transposed fp16 [C,R]
__global__ void conv_t(const float* __restrict__ X, int ldx,
                       hf* __restrict__ Oh, int ldo, int R, int C)
{
    __shared__ float s[32][33];
    const int c0 = blockIdx.x * 32, r0 = blockIdx.y * 32;
    const int tx = threadIdx.x, ty = threadIdx.y;
#pragma unroll
    for (int i = 0; i < 4; i++) {
        int r = r0 + ty + i * 8, c = c0 + tx;
        if (r < R && c < C) s[ty + i * 8][tx] = X[(long)r * ldx + c];
    }
    __syncthreads();
#pragma unroll
    for (int i = 0; i < 4; i++) {
        int oc = c0 + ty + i * 8, orr = r0 + tx;
        if (oc < C && orr < R)
            Oh[(long)oc * ldo + orr] = __float2half(s[tx][ty + i * 8]);
    }
}

// fp16 [R,C] (batched view) -> transposed fp16 [C,R]
__global__ void conv_t16(const hf* __restrict__ X, int ldx, long sXb, long sXh,
                         hf* __restrict__ Oh, int ldo, long sO, int R, int C)
{
    __shared__ uint16_t s[32][34];
    const int z = blockIdx.z;
    X  += (long)(z >> 4) * sXb + (long)(z & 15) * sXh;
    Oh += (long)z * sO;
    const int c0 = blockIdx.x * 32, r0 = blockIdx.y * 32;
    const int tx = threadIdx.x, ty = threadIdx.y;
#pragma unroll
    for (int i = 0; i < 4; i++) {
        int r = r0 + ty + i * 8, c = c0 + tx;
        if (r < R && c < C)
            s[ty + i * 8][tx] = ((const uint16_t*)X)[(long)r * ldx + c];
    }
    __syncthreads();
#pragma unroll
    for (int i = 0; i < 4; i++) {
        int oc = c0 + ty + i * 8, orr = r0 + tx;
        if (oc < C && orr < R)
            ((uint16_t*)Oh)[(long)oc * ldo + orr] = s[tx][ty + i * 8];
    }
}

// Merged rmsnorms: gridDim.y = 2 selects q-part / kv-part
__global__ void rmsnorm2(const float* __restrict__ kvq,
                         const float* __restrict__ wq, const float* __restrict__ wkv,
                         hf* __restrict__ yq, hf* __restrict__ ykv)
{
    const int row  = blockIdx.x;
    const int part = blockIdx.y;
    const float* xr = kvq + (long)row * W1N + (part ? QR_ : 0);
    const float* w  = part ? wkv : wq;
    hf* y = part ? (ykv + (long)row * KVR_) : (yq + (long)row * QR_);
    const int cols = part ? KVR_ : QR_;
    const int t = threadIdx.x;
    float ss = 0.f;
    for (int c = t; c < cols; c += 256) { float v = xr[c]; ss += v * v; }
    __shared__ float sh[8];
#pragma unroll
    for (int o = 16; o > 0; o >>= 1) ss += __shfl_xor_sync(~0u, ss, o);
    if ((t & 31) == 0) sh[t >> 5] = ss;
    __syncthreads();
    float tot = 0.f;
#pragma unroll
    for (int i = 0; i < 8; i++) tot += sh[i];
    float inv = rsqrtf(tot / (float)cols + 1e-6f);
    for (int c = t; c < cols; c += 256)
        y[c] = __float2half(xr[c] * inv * w[c]);
}

// k_rope: broadcast across heads. grid (S_, B_), 64 threads.
__global__ void build_ks_rope(const float* __restrict__ kvq,
                              const int* __restrict__ pos, hf* __restrict__ ks)
{
    const int s = blockIdx.x, b = blockIdx.y;
    const int j = threadIdx.x;                 // 0..63
    const long tok = (long)b * S_ + s;
    const float* kr = kvq + tok * W1N + QR_ + KVR_;
    float c, sn; rope_cs(pos[s], j & 31, c, sn);
    float xo = (j < 32) ? -kr[j + 32] : kr[j - 32];
    hf v = __float2half(kr[j] * c + xo * sn);
#pragma unroll
    for (int h = 0; h < NH_; h++)
        ks[(((long)(b * NH_ + h)) * S_ + s) * QD_ + DN_ + j] = v;
}

// Normalize: read fp16 unnormalized exp row, write fp32 attn row + 1/sum.
__global__ void attn_norm(const hf* __restrict__ pp, float* __restrict__ attn,
                          float* __restrict__ invs)
{
    const long row = blockIdx.x;
    const int t = threadIdx.x;

    uint4 pk = ((const uint4*)(pp + row * (long)S_))[t];
    __half2 h0 = *(__half2*)&pk.x, h1 = *(__half2*)&pk.y;
    __half2 h2 = *(__half2*)&pk.z, h3 = *(__half2*)&pk.w;
    float v[8];
    v[0] = __half2float(__low2half(h0));  v[1] = __half2float(__high2half(h0));
    v[2] = __half2float(__low2half(h1));  v[3] = __half2float(__high2half(h1));
    v[4] = __half2float(__low2half(h2));  v[5] = __half2float(__high2half(h2));
    v[6] = __half2float(__low2half(h3));  v[7] = __half2float(__high2half(h3));

    float sum = 0.f;
#pragma unroll
    for (int i = 0; i < 8; i++) sum += v[i];

    __shared__ float sh[8];
#pragma unroll
    for (int o = 16; o > 0; o >>= 1) sum += __shfl_xor_sync(~0u, sum, o);
    if ((t & 31) == 0) sh[t >> 5] = sum;
    __syncthreads();
    float tot = 0.f;
#pragma unroll
    for (int i = 0; i < 8; i++) tot += sh[i];

    float inv = 1.f / tot;
    float* ar = attn + row * (long)S_;
    ((float4*)ar)[t * 2]     = make_float4(v[0] * inv, v[1] * inv, v[2] * inv, v[3] * inv);
    ((float4*)ar)[t * 2 + 1] = make_float4(v[4] * inv, v[5] * inv, v[6] * inv, v[7] * inv);
    if (t == 0) invs[row] = inv;
}

// ---------------------------------------------------------------------------
extern "C" void kernel_launch(void* const* d_in, const int* in_sizes, int n_in,
                              void* d_out, int out_size)
{
    const float* hidden    = (const float*)d_in[0];
    const int*   pos       = (const int*)  d_in[1];
    const float* q_down_W  = (const float*)d_in[2];
    const float* q_norm_w  = (const float*)d_in[3];
    const float* q_up_W    = (const float*)d_in[4];
    const float* kv_down_W = (const float*)d_in[5];
    const float* kv_norm_w = (const float*)d_in[6];
    const float* kv_up_W   = (const float*)d_in[7];
    const float* out_W     = (const float*)d_in[8];

    float* out  = (float*)d_out;
    float* attn = out + (long)B_ * S_ * H_;

#define SYM(p, s) cudaGetSymbolAddress((void**)&p, s)
    hf *hid_h, *w1, *qup_h, *kvupw_h, *outw_h;
    hf *qlat_h, *kvlat_h, *kvup_h;
    hf *qs_h, *ks_h, *vt_h, *at_h, *ao_h;
    float *kvq, *invs;
    SYM(hid_h, g_hid_h);
    SYM(w1, g_w1);           SYM(qup_h, g_qup_h);
    SYM(kvupw_h, g_kvupw_h); SYM(outw_h, g_outw_h);
    SYM(qlat_h, g_qlat_h);   SYM(kvlat_h, g_kvlat_h);
    SYM(kvup_h, g_kvup_h);
    SYM(qs_h, g_qs_h);       SYM(ks_h, g_ks_h);
    SYM(vt_h, g_vt_h);       SYM(at_h, g_at_h);
    SYM(ao_h, g_ao_h);
    SYM(kvq, g_kvq);         SYM(invs, g_invs);
#undef SYM

    const int SM_128_256_1 = 3 * (1 * 256 * LDT * 2 + 128 * LDT * 2);  // 165888
    const int SM_256_128_1 = 3 * (1 * 128 * LDT * 2 + 256 * LDT * 2);  // 165888

    cudaFuncSetAttribute(gemm_t<256,128,1,2>, cudaFuncAttributeMaxDynamicSharedMemorySize, SM_256_128_1);
    cudaFuncSetAttribute(gemm_t<128,256,1,1>, cudaFuncAttributeMaxDynamicSharedMemorySize, SM_128_256_1);
    cudaFuncSetAttribute(gemm_t<256,128,1,0>, cudaFuncAttributeMaxDynamicSharedMemorySize, SM_256_128_1);
    cudaFuncSetAttribute(gemm_pair,           cudaFuncAttributeMaxDynamicSharedMemorySize, SM_256_128_1);

    dim3 tb(32, 8);

    // weight transposes + hidden convert
    conv_t<<<dim3(48, 64, 1), tb>>>(q_down_W, QR_, w1, H_, H_, QR_);
    conv_h<<<(TOK*H_/4 + 255)/256, 256>>>((const float4*)hidden, hid_h, TOK*H_/4);
    conv_t<<<dim3(18, 64, 1), tb>>>(kv_down_W, KVR_+DR_, w1 + (long)QR_*H_, H_, H_, KVR_+DR_);
    conv_t<<<dim3(96, 48, 1), tb>>>(q_up_W, NH_*QD_, qup_h, QR_, QR_, NH_*QD_);
    conv_t<<<dim3(128, 16, 1), tb>>>(kv_up_W, 4096, kvupw_h, KVR_, KVR_, 4096);

    // merged [qlat | kv] = hidden @ [q_down_W | kv_down_W]   (N=2112, fp32 out)
    gemm_t<256,128,1,0><<<dim3(9, 32, 1), 256, SM_256_128_1>>>(
        hid_h, nullptr, 0, H_, w1, 0, H_,
        kvq, 0, 0, W1N, nullptr, W1N, H_, 1.f);

    conv_t<<<dim3(64, 64, 1), tb>>>(out_W, H_, outw_h, NH_*DV_, NH_*DV_, H_);

    // merged rmsnorms -> fp16
    rmsnorm2<<<dim3(TOK, 2), 256>>>(kvq, q_norm_w, kv_norm_w, qlat_h, kvlat_h);
    // k_rope (broadcast across heads) straight into ks
    build_ks_rope<<<dim3(S_, B_), 64>>>(kvq, pos, ks_h);

    // qup (-> qs with RoPE fused) + kvup (-> ks k_nope + kvup_h v) in one launch
    gemm_pair<<<384 + 512, 256, SM_256_128_1>>>(
        qlat_h, qup_h, QR_, 12, 384,
        kvlat_h, kvupw_h, KVR_, 16,
        pos, qs_h, ks_h, kvup_h);

    // v^T per (b,h): [dv, s] from fp16 kvup v-region
    conv_t16<<<dim3(4, 64, ZBH), tb>>>(kvup_h + DN_, 4096, (long)S_*4096, 256,
                                       vt_h, S_, (long)DV_*S_, S_, DV_);
    // p = exp(scale*Q@K^T - OFF) -> fp16 at_h
    gemm_t<256,128,1,2><<<dim3(8, 16, ZBH), 256, SM_256_128_1>>>(
        qs_h, nullptr, (long)S_*QD_, QD_, ks_h, (long)S_*QD_, QD_,
        at_h, (long)NH_*S_*S_, (long)S_*S_, S_,
        nullptr, S_, QD_, 0.0721687836487032f);
    // normalize: fp32 attn output + 1/rowsum
    attn_norm<<<ZBH*S_, 256>>>(at_h, attn, invs);
    // pv = p @ Vh scaled by 1/rowsum -> fp16 token-major
    gemm_t<128,256,1,1><<<dim3(1, 8, ZBH), 256, SM_128_256_1>>>(
        at_h, nullptr, (long)S_*S_, S_, vt_h, (long)DV_*S_, S_,
        ao_h, (long)S_*2048, DV_, 2048,
        invs, DV_, S_, 1.f);
    // out = ao_h @ out_W
    gemm_t<256,128,1,0><<<dim3(8, 32, 1), 256, SM_256_128_1>>>(
        ao_h, nullptr, 0, NH_*DV_, outw_h, 0, NH_*DV_,
        out, 0, 0, H_, nullptr, H_, NH_*DV_, 1.f);
}

// round 16
// speedup vs baseline: 1.0313x; 1.0313x over previous
#include <cuda_runtime.h>
#include <cuda_fp16.h>
#include <math.h>
#include <stdint.h>

typedef __half hf;

// Problem constants
#define B_   2
#define S_   2048
#define H_   2048
#define NH_  16
#define DN_  128
#define DR_  64
#define DV_  128
#define QR_  1536
#define KVR_ 512
#define QD_  192
#define TOK  (B_*S_)          // 4096
#define ZBH  (B_*NH_)         // 32
#define W1N  (QR_ + KVR_ + DR_)   // 2112

#define EXP_OFF 5.0f

// ---------------------------------------------------------------------------
// Scratch (device globals)
// ---------------------------------------------------------------------------
__device__ hf  g_hid_h [TOK*2048];
__device__ hf  g_w1    [W1N*2048];
__device__ hf  g_qup_h [3072*1536];
__device__ hf  g_kvupw_h[4096*512];
__device__ hf  g_outw_h[2048*2048];
__device__ float g_kvq [TOK*W1N];
__device__ hf  g_qlat_h[TOK*QR_];
__device__ hf  g_kvlat_h[TOK*KVR_];
__device__ hf  g_qf_h  [TOK*(NH_*QD_)];
__device__ hf  g_kvup_h[TOK*4096];
__device__ hf  g_qs_h  [(size_t)ZBH*S_*QD_];
__device__ hf  g_ks_h  [(size_t)ZBH*S_*QD_];
__device__ hf  g_vt_h  [(size_t)ZBH*DV_*S_];
__device__ hf  g_at_h  [(size_t)ZBH*S_*S_];
__device__ float g_invs[(size_t)ZBH*S_];
__device__ hf  g_ao_h  [TOK*2048];

// ---------------------------------------------------------------------------
// Portable PTX helpers
// ---------------------------------------------------------------------------
__device__ __forceinline__ uint32_t smem_u32(const void* p) {
    uint32_t a;
    asm("{ .reg .u64 t; cvta.to.shared.u64 t, %1; cvt.u32.u64 %0, t; }"
        : "=r"(a) : "l"(p));
    return a;
}

__device__ __forceinline__ void ldsm4(uint32_t* r, uint32_t addr) {
    asm volatile("ldmatrix.sync.aligned.m8n8.x4.shared.b16 {%0,%1,%2,%3}, [%4];"
        : "=r"(r[0]), "=r"(r[1]), "=r"(r[2]), "=r"(r[3]) : "r"(addr));
}

__device__ __forceinline__ void mma16816(float* c, const uint32_t* a, const uint32_t* b) {
    asm volatile(
        "mma.sync.aligned.m16n8k16.row.col.f32.f16.f16.f32 "
        "{%0,%1,%2,%3}, {%4,%5,%6,%7}, {%8,%9}, {%0,%1,%2,%3};"
        : "+f"(c[0]), "+f"(c[1]), "+f"(c[2]), "+f"(c[3])
        : "r"(a[0]), "r"(a[1]), "r"(a[2]), "r"(a[3]), "r"(b[0]), "r"(b[1]));
}

__device__ __forceinline__ void cp16(uint32_t dst, const void* src, bool v) {
    int sz = v ? 16 : 0;
    asm volatile("cp.async.cg.shared.global [%0], [%1], 16, %2;"
                 :: "r"(dst), "l"(src), "r"(sz) : "memory");
}

template<int W> __device__ __forceinline__ void cp_wait() {
    asm volatile("cp.async.wait_group %0;" :: "n"(W) : "memory");
}

__device__ __forceinline__ void rope_cs(int pos, int f, float& c, float& s)
{
    float invf = (float)exp(-(double)f * 9.210340371976184 / 32.0);
    float arg = (float)pos * invf;
    c = cosf(arg); s = sinf(arg);
}

#define LDT      72                    // padded row stride in halves (144 B)

template<int NT, int MT, int P>
__device__ __forceinline__ void load_stage(
    uint32_t sbase, int kc, int tid, int m0, int n0, int N,
    const hf* __restrict__ Ah, const hf* __restrict__ Al, int lda,
    const hf* __restrict__ Bh, int ldb)
{
    constexpr int TILE_A = MT * LDT * 2;
    const int ROWS = P * MT + NT;
    const int ITERS = ROWS / 32;
#pragma unroll
    for (int it = 0; it < ITERS; it++) {
        int idx = tid + it * 256;
        int r = idx >> 3, sg = idx & 7;
        if (r < MT) {
            cp16(sbase + (uint32_t)(r * LDT + sg * 8) * 2,
                 Ah + (long)(m0 + r) * lda + kc + sg * 8, true);
        } else if (P == 2 && r < 2 * MT) {
            int rr = r - MT;
            cp16(sbase + TILE_A + (uint32_t)(rr * LDT + sg * 8) * 2,
                 Al + (long)(m0 + rr) * lda + kc + sg * 8, true);
        } else {
            int rr = r - P * MT;
            bool bv = (n0 + rr) < N;
            cp16(sbase + P * TILE_A + (uint32_t)(rr * LDT + sg * 8) * 2,
                 Bh + (long)(bv ? n0 + rr : 0) * ldb + kc + sg * 8, bv);
        }
    }
    asm volatile("cp.async.commit_group;" ::: "memory");
}

// ---------------------------------------------------------------------------
// Main templated GEMM. EMODE 0: fp32 direct; 1: fp16*rowscale (smem-staged);
// 2: fp16 exp (smem-staged).
// ---------------------------------------------------------------------------
template<int NT, int MT, int P, int EMODE>
__global__ __launch_bounds__(256, 1)
void gemm_t(const hf* __restrict__ Ah, const hf* __restrict__ Al,
            long sA, int lda,
            const hf* __restrict__ Bh, long sB, int ldb,
            void* __restrict__ C0, long sCb, long sCh, int ldc,
            const float* __restrict__ rowscale,
            int N, int K, float alpha)
{
    constexpr int MW = MT / 64;
    constexpr int NW = 8 / MW;
    constexpr int WN = NT / NW;
    constexpr int NI = WN / 8;
    constexpr int NG = WN / 16;
    constexpr int TILE_A = MT * LDT * 2;
    constexpr int STAGE_B = P * TILE_A + NT * LDT * 2;
    constexpr int SST = NT + 8;            // epilogue stage stride (halves)

    extern __shared__ char smem[];
    const uint32_t smb = smem_u32(smem);

    const int tid  = threadIdx.x;
    const int lane = tid & 31;
    const int wid  = tid >> 5;
    const int wm   = wid / NW;
    const int wn   = wid % NW;
    const int z    = blockIdx.z;
    const int m0   = blockIdx.y * MT;
    const int n0   = blockIdx.x * NT;

    Ah += (long)z * sA;  if (P == 2) Al += (long)z * sA;
    Bh += (long)z * sB;
    const long coff = (long)(z >> 4) * sCb + (long)(z & 15) * sCh;

    float acc[4][NI][4];
#pragma unroll
    for (int mi = 0; mi < 4; mi++)
#pragma unroll
        for (int ni = 0; ni < NI; ni++)
#pragma unroll
            for (int j = 0; j < 4; j++) acc[mi][ni][j] = 0.f;

    const int NC = K / 64;

    load_stage<NT, MT, P>(smb, 0, tid, m0, n0, N, Ah, Al, lda, Bh, ldb);
    load_stage<NT, MT, P>(smb + STAGE_B, 64, tid, m0, n0, N, Ah, Al, lda, Bh, ldb);

    const int a_r = (lane & 15);
    const int a_k = (lane >> 4) << 3;
    const int b_n = ((lane >> 4) << 3) + (lane & 7);
    const int b_k = ((lane >> 3) & 1) << 3;

    int stage = 0;
    for (int c = 0; c < NC; c++) {
        if (c + 2 < NC) {
            int ns = stage + 2; if (ns >= 3) ns -= 3;
            load_stage<NT, MT, P>(smb + ns * STAGE_B, (c + 2) * 64, tid, m0, n0, N,
                                  Ah, Al, lda, Bh, ldb);
            cp_wait<2>();
        } else if (c + 1 < NC) {
            cp_wait<1>();
        } else {
            cp_wait<0>();
        }
        __syncthreads();

        const uint32_t sbase = smb + stage * STAGE_B;

#pragma unroll
        for (int ks = 0; ks < 64; ks += 16) {
            uint32_t aH[4][4], aX[P == 2 ? 4 : 1][4], bH[NG][4];
#pragma unroll
            for (int mi = 0; mi < 4; mi++) {
                uint32_t off = (uint32_t)((wm * 64 + mi * 16 + a_r) * LDT + ks + a_k) * 2;
                ldsm4(aH[mi], sbase + off);
                if (P == 2) ldsm4(aX[mi], sbase + TILE_A + off);
            }
#pragma unroll
            for (int g = 0; g < NG; g++) {
                uint32_t off = (uint32_t)((wn * WN + g * 16 + b_n) * LDT + ks + b_k) * 2;
                ldsm4(bH[g], sbase + P * TILE_A + off);
            }
#pragma unroll
            for (int p = 0; p < P; p++) {
#pragma unroll
                for (int mi = 0; mi < 4; mi++)
#pragma unroll
                    for (int ni = 0; ni < NI; ni++)
                        mma16816(acc[mi][ni],
                                 (p == 1) ? aX[mi] : aH[mi],
                                 &bH[ni >> 1][(ni & 1) * 2]);
            }
        }
        __syncthreads();
        stage++; if (stage == 3) stage = 0;
    }

    if (EMODE == 0) {
        // fp32 direct (float2 = full 32B sectors per quarter-warp)
#pragma unroll
        for (int mi = 0; mi < 4; mi++) {
            int r0 = m0 + wm * 64 + mi * 16 + (lane >> 2);
#pragma unroll
            for (int ni = 0; ni < NI; ni++) {
                int col = n0 + wn * WN + ni * 8 + (lane & 3) * 2;
                if (col >= N) continue;
                float* C = (float*)C0 + coff;
                *(float2*)&C[(long)r0 * ldc + col] =
                    make_float2(alpha * acc[mi][ni][0], alpha * acc[mi][ni][1]);
                *(float2*)&C[(long)(r0 + 8) * ldc + col] =
                    make_float2(alpha * acc[mi][ni][2], alpha * acc[mi][ni][3]);
            }
        }
    } else {
        // fp16: stage via smem, then coalesced uint4 stores
        hf* sc = (hf*)smem;
#pragma unroll
        for (int mi = 0; mi < 4; mi++) {
            int rr = wm * 64 + mi * 16 + (lane >> 2);
            float is0 = 1.f, is1 = 1.f;
            if (EMODE == 1) {
                is0 = rowscale[(long)z * S_ + m0 + rr];
                is1 = rowscale[(long)z * S_ + m0 + rr + 8];
            }
#pragma unroll
            for (int ni = 0; ni < NI; ni++) {
                int cc = wn * WN + ni * 8 + (lane & 3) * 2;
                float v0 = alpha * acc[mi][ni][0], v1 = alpha * acc[mi][ni][1];
                float v2 = alpha * acc[mi][ni][2], v3 = alpha * acc[mi][ni][3];
                if (EMODE == 2) {
                    const float L2E = 1.44269504f, OF2 = EXP_OFF * 1.44269504f;
                    v0 = exp2f(v0 * L2E - OF2);
                    v1 = exp2f(v1 * L2E - OF2);
                    v2 = exp2f(v2 * L2E - OF2);
                    v3 = exp2f(v3 * L2E - OF2);
                } else {
                    v0 *= is0; v1 *= is0; v2 *= is1; v3 *= is1;
                }
                *(__half2*)&sc[rr * SST + cc] =
                    __halves2half2(__float2half(v0), __float2half(v1));
                *(__half2*)&sc[(rr + 8) * SST + cc] =
                    __halves2half2(__float2half(v2), __float2half(v3));
            }
        }
        __syncthreads();
        hf* C = (hf*)C0 + coff;
        constexpr int CP8 = NT / 8;
        constexpr int IT2 = MT * NT / 8 / 256;
#pragma unroll
        for (int it = 0; it < IT2; it++) {
            int idx = tid + it * 256;
            int row = idx / CP8, c8 = idx % CP8;
            int col = n0 + c8 * 8;
            if (col < N)
                *(uint4*)&C[(long)(m0 + row) * ldc + col] =
                    *(uint4*)&sc[row * SST + c8 * 8];
        }
    }
}

// ---------------------------------------------------------------------------
// gemm_pair: qup + kvup in one launch (fp16 out, smem-staged stores).
// ---------------------------------------------------------------------------
__global__ __launch_bounds__(256, 1)
void gemm_pair(const hf* __restrict__ A0, int lda0, const hf* __restrict__ B0,
               int ldb0, hf* __restrict__ C0p, int ldc0, int N0, int K0, int nx0,
               int nc0,
               const hf* __restrict__ A1, int lda1, const hf* __restrict__ B1,
               int ldb1, hf* __restrict__ C1p, int ldc1, int N1, int K1, int nx1)
{
    constexpr int NT = 256, MT = 128;
    constexpr int STAGE_B = MT * LDT * 2 + NT * LDT * 2;
    constexpr int SST = NT + 8;

    extern __shared__ char smem[];
    const uint32_t smb = smem_u32(smem);

    const int tid  = threadIdx.x;
    const int lane = tid & 31;
    const int wid  = tid >> 5;
    const int wm   = wid / 4;
    const int wn   = wid % 4;

    const hf* Ah; const hf* Bh; hf* C;
    int lda, ldb, ldc, N, K, bx, by;
    {
        int id = blockIdx.x;
        if (id < nc0) {
            Ah = A0; Bh = B0; C = C0p; lda = lda0; ldb = ldb0; ldc = ldc0;
            N = N0; K = K0; bx = id % nx0; by = id / nx0;
        } else {
            id -= nc0;
            Ah = A1; Bh = B1; C = C1p; lda = lda1; ldb = ldb1; ldc = ldc1;
            N = N1; K = K1; bx = id % nx1; by = id / nx1;
        }
    }
    const int m0 = by * MT;
    const int n0 = bx * NT;

    float acc[4][8][4];
#pragma unroll
    for (int mi = 0; mi < 4; mi++)
#pragma unroll
        for (int ni = 0; ni < 8; ni++)
#pragma unroll
            for (int j = 0; j < 4; j++) acc[mi][ni][j] = 0.f;

    const int NC = K / 64;

    load_stage<NT, MT, 1>(smb, 0, tid, m0, n0, N, Ah, nullptr, lda, Bh, ldb);
    load_stage<NT, MT, 1>(smb + STAGE_B, 64, tid, m0, n0, N, Ah, nullptr, lda, Bh, ldb);

    const int a_r = (lane & 15);
    const int a_k = (lane >> 4) << 3;
    const int b_n = ((lane >> 4) << 3) + (lane & 7);
    const int b_k = ((lane >> 3) & 1) << 3;

    int stage = 0;
    for (int c = 0; c < NC; c++) {
        if (c + 2 < NC) {
            int ns = stage + 2; if (ns >= 3) ns -= 3;
            load_stage<NT, MT, 1>(smb + ns * STAGE_B, (c + 2) * 64, tid, m0, n0, N,
                                  Ah, nullptr, lda, Bh, ldb);
            cp_wait<2>();
        } else if (c + 1 < NC) {
            cp_wait<1>();
        } else {
            cp_wait<0>();
        }
        __syncthreads();

        const uint32_t sbase = smb + stage * STAGE_B;

#pragma unroll
        for (int ks = 0; ks < 64; ks += 16) {
            uint32_t aH[4][4], bH[4][4];
#pragma unroll
            for (int mi = 0; mi < 4; mi++) {
                uint32_t off = (uint32_t)((wm * 64 + mi * 16 + a_r) * LDT + ks + a_k) * 2;
                ldsm4(aH[mi], sbase + off);
            }
#pragma unroll
            for (int g = 0; g < 4; g++) {
                uint32_t off = (uint32_t)((wn * 64 + g * 16 + b_n) * LDT + ks + b_k) * 2;
                ldsm4(bH[g], sbase + MT * LDT * 2 + off);
            }
#pragma unroll
            for (int mi = 0; mi < 4; mi++)
#pragma unroll
                for (int ni = 0; ni < 8; ni++)
                    mma16816(acc[mi][ni], aH[mi], &bH[ni >> 1][(ni & 1) * 2]);
        }
        __syncthreads();
        stage++; if (stage == 3) stage = 0;
    }

    // smem-staged fp16 epilogue
    hf* sc = (hf*)smem;
#pragma unroll
    for (int mi = 0; mi < 4; mi++) {
        int rr = wm * 64 + mi * 16 + (lane >> 2);
#pragma unroll
        for (int ni = 0; ni < 8; ni++) {
            int cc = wn * 64 + ni * 8 + (lane & 3) * 2;
            *(__half2*)&sc[rr * SST + cc] =
                __halves2half2(__float2half(acc[mi][ni][0]), __float2half(acc[mi][ni][1]));
            *(__half2*)&sc[(rr + 8) * SST + cc] =
                __halves2half2(__float2half(acc[mi][ni][2]), __float2half(acc[mi][ni][3]));
        }
    }
    __syncthreads();
#pragma unroll
    for (int it = 0; it < 16; it++) {
        int idx = tid + it * 256;
        int row = idx >> 5, c8 = idx & 31;
        int col = n0 + c8 * 8;
        if (col < N)
            *(uint4*)&C[(long)(m0 + row) * ldc + col] =
                *(uint4*)&sc[row * SST + c8 * 8];
    }
}

// ---------------------------------------------------------------------------
// Elementwise / conversion kernels
// ---------------------------------------------------------------------------
__global__ void conv_h(const float4* __restrict__ x, hf* __restrict__ h, int n4)
{
    int i = blockIdx.x * 256 + threadIdx.x;
    if (i >= n4) return;
    float4 v = x[i];
    __half2 a = __halves2half2(__float2half(v.x), __float2half(v.y));
    __half2 b = __halves2half2(__float2half(v.z), __float2half(v.w));
    uint2 pk; pk.x = *(uint32_t*)&a; pk.y = *(uint32_t*)&b;
    ((uint2*)h)[i] = pk;
}

__global__ void conv_t(const float* __restrict__ X, int ldx,
                       hf* __restrict__ Oh, int ldo, int R, int C)
{
    __shared__ float s[32][33];
    const int c0 = blockIdx.x * 32, r0 = blockIdx.y * 32;
    const int tx = threadIdx.x, ty = threadIdx.y;
#pragma unroll
    for (int i = 0; i < 4; i++) {
        int r = r0 + ty + i * 8, c = c0 + tx;
        if (r < R && c < C) s[ty + i * 8][tx] = X[(long)r * ldx + c];
    }
    __syncthreads();
#pragma unroll
    for (int i = 0; i < 4; i++) {
        int oc = c0 + ty + i * 8, orr = r0 + tx;
        if (oc < C && orr < R)
            Oh[(long)oc * ldo + orr] = __float2half(s[tx][ty + i * 8]);
    }
}

__global__ void conv_t16(const hf* __restrict__ X, int ldx, long sXb, long sXh,
                         hf* __restrict__ Oh, int ldo, long sO, int R, int C)
{
    __shared__ uint16_t s[32][34];
    const int z = blockIdx.z;
    X  += (long)(z >> 4) * sXb + (long)(z & 15) * sXh;
    Oh += (long)z * sO;
    const int c0 = blockIdx.x * 32, r0 = blockIdx.y * 32;
    const int tx = threadIdx.x, ty = threadIdx.y;
#pragma unroll
    for (int i = 0; i < 4; i++) {
        int r = r0 + ty + i * 8, c = c0 + tx;
        if (r < R && c < C)
            s[ty + i * 8][tx] = ((const uint16_t*)X)[(long)r * ldx + c];
    }
    __syncthreads();
#pragma unroll
    for (int i = 0; i < 4; i++) {
        int oc = c0 + ty + i * 8, orr = r0 + tx;
        if (oc < C && orr < R)
            ((uint16_t*)Oh)[(long)oc * ldo + orr] = s[tx][ty + i * 8];
    }
}

__global__ void rmsnorm2(const float* __restrict__ kvq,
                         const float* __restrict__ wq, const float* __restrict__ wkv,
                         hf* __restrict__ yq, hf* __restrict__ ykv)
{
    const int row  = blockIdx.x;
    const int part = blockIdx.y;
    const float* xr = kvq + (long)row * W1N + (part ? QR_ : 0);
    const float* w  = part ? wkv : wq;
    hf* y = part ? (ykv + (long)row * KVR_) : (yq + (long)row * QR_);
    const int cols = part ? KVR_ : QR_;
    const int t = threadIdx.x;
    float ss = 0.f;
    for (int c = t; c < cols; c += 256) { float v = xr[c]; ss += v * v; }
    __shared__ float sh[8];
#pragma unroll
    for (int o = 16; o > 0; o >>= 1) ss += __shfl_xor_sync(~0u, ss, o);
    if ((t & 31) == 0) sh[t >> 5] = ss;
    __syncthreads();
    float tot = 0.f;
#pragma unroll
    for (int i = 0; i < 8; i++) tot += sh[i];
    float inv = rsqrtf(tot / (float)cols + 1e-6f);
    for (int c = t; c < cols; c += 256)
        y[c] = __float2half(xr[c] * inv * w[c]);
}

// q states, vectorized half2: [tok, h*192] -> [z][s][192]
__global__ void build_qs2(const hf* __restrict__ q, const int* __restrict__ pos,
                          hf* __restrict__ qh)
{
    int f = blockIdx.x * 256 + threadIdx.x;        // half2 index
    int o = f * 2;
    int z = o / (S_ * QD_);
    int r = o - z * (S_ * QD_);
    int s = r / QD_;
    int dd = r - s * QD_;
    int b = z >> 4, h = z & 15;
    const hf* src = q + ((long)(b * S_ + s)) * (NH_ * QD_) + h * QD_;
    __half2 v;
    if (dd < DN_) {
        v = *(const __half2*)&src[dd];
    } else {
        int j = dd - DN_;
        float x0 = __half2float(src[dd]), x1 = __half2float(src[dd + 1]);
        float sgn = (j < 32) ? -1.f : 1.f;
        int pj = (j < 32) ? dd + 32 : dd - 32;
        float p0 = __half2float(src[pj]), p1 = __half2float(src[pj + 1]);
        float c0, s0, c1, s1;
        rope_cs(pos[s], j & 31, c0, s0);
        rope_cs(pos[s], (j + 1) & 31, c1, s1);
        v = __halves2half2(__float2half(x0 * c0 + sgn * p0 * s0),
                           __float2half(x1 * c1 + sgn * p1 * s1));
    }
    *(__half2*)&qh[(long)z * (S_ * QD_) + r] = v;
}

// k states, vectorized half2: nope from fp16 kvup, rope from fp32 kvq cols
__global__ void build_ks2(const hf* __restrict__ kvup, const float* __restrict__ kvq,
                          const int* __restrict__ pos, hf* __restrict__ kh)
{
    int f = blockIdx.x * 256 + threadIdx.x;
    int o = f * 2;
    int z = o / (S_ * QD_);
    int r = o - z * (S_ * QD_);
    int s = r / QD_;
    int dd = r - s * QD_;
    int b = z >> 4, h = z & 15;
    const long tok = (long)b * S_ + s;
    __half2 v;
    if (dd < DN_) {
        v = *(const __half2*)&kvup[tok * 4096 + h * 256 + dd];
    } else {
        int j = dd - DN_;
        const float* kr = kvq + tok * W1N + QR_ + KVR_;
        float sgn = (j < 32) ? -1.f : 1.f;
        int pj = (j < 32) ? j + 32 : j - 32;
        float c0, s0, c1, s1;
        rope_cs(pos[s], j & 31, c0, s0);
        rope_cs(pos[s], (j + 1) & 31, c1, s1);
        v = __halves2half2(__float2half(kr[j] * c0 + sgn * kr[pj] * s0),
                           __float2half(kr[j + 1] * c1 + sgn * kr[pj + 1] * s1));
    }
    *(__half2*)&kh[(long)z * (S_ * QD_) + r] = v;
}

// Normalize: read fp16 unnormalized exp row, write fp32 attn row + 1/sum.
__global__ void attn_norm(const hf* __restrict__ pp, float* __restrict__ attn,
                          float* __restrict__ invs)
{
    const long row = blockIdx.x;
    const int t = threadIdx.x;

    uint4 pk = ((const uint4*)(pp + row * (long)S_))[t];
    __half2 h0 = *(__half2*)&pk.x, h1 = *(__half2*)&pk.y;
    __half2 h2 = *(__half2*)&pk.z, h3 = *(__half2*)&pk.w;
    float v[8];
    v[0] = __half2float(__low2half(h0));  v[1] = __half2float(__high2half(h0));
    v[2] = __half2float(__low2half(h1));  v[3] = __half2float(__high2half(h1));
    v[4] = __half2float(__low2half(h2));  v[5] = __half2float(__high2half(h2));
    v[6] = __half2float(__low2half(h3));  v[7] = __half2float(__high2half(h3));

    float sum = 0.f;
#pragma unroll
    for (int i = 0; i < 8; i++) sum += v[i];

    __shared__ float sh[8];
#pragma unroll
    for (int o = 16; o > 0; o >>= 1) sum += __shfl_xor_sync(~0u, sum, o);
    if ((t & 31) == 0) sh[t >> 5] = sum;
    __syncthreads();
    float tot = 0.f;
#pragma unroll
    for (int i = 0; i < 8; i++) tot += sh[i];

    float inv = 1.f / tot;
    float* ar = attn + row * (long)S_;
    __stcs((float4*)ar + t * 2,
           make_float4(v[0] * inv, v[1] * inv, v[2] * inv, v[3] * inv));
    __stcs((float4*)ar + t * 2 + 1,
           make_float4(v[4] * inv, v[5] * inv, v[6] * inv, v[7] * inv));
    if (t == 0) invs[row] = inv;
}

// ---------------------------------------------------------------------------
extern "C" void kernel_launch(void* const* d_in, const int* in_sizes, int n_in,
                              void* d_out, int out_size)
{
    const float* hidden    = (const float*)d_in[0];
    const int*   pos       = (const int*)  d_in[1];
    const float* q_down_W  = (const float*)d_in[2];
    const float* q_norm_w  = (const float*)d_in[3];
    const float* q_up_W    = (const float*)d_in[4];
    const float* kv_down_W = (const float*)d_in[5];
    const float* kv_norm_w = (const float*)d_in[6];
    const float* kv_up_W   = (const float*)d_in[7];
    const float* out_W     = (const float*)d_in[8];

    float* out  = (float*)d_out;
    float* attn = out + (long)B_ * S_ * H_;

#define SYM(p, s) cudaGetSymbolAddress((void**)&p, s)
    hf *hid_h, *w1, *qup_h, *kvupw_h, *outw_h;
    hf *qlat_h, *kvlat_h, *qf_h, *kvup_h;
    hf *qs_h, *ks_h, *vt_h, *at_h, *ao_h;
    float *kvq, *invs;
    SYM(hid_h, g_hid_h);
    SYM(w1, g_w1);           SYM(qup_h, g_qup_h);
    SYM(kvupw_h, g_kvupw_h); SYM(outw_h, g_outw_h);
    SYM(qlat_h, g_qlat_h);   SYM(kvlat_h, g_kvlat_h);
    SYM(qf_h, g_qf_h);       SYM(kvup_h, g_kvup_h);
    SYM(qs_h, g_qs_h);       SYM(ks_h, g_ks_h);
    SYM(vt_h, g_vt_h);       SYM(at_h, g_at_h);
    SYM(ao_h, g_ao_h);
    SYM(kvq, g_kvq);         SYM(invs, g_invs);
#undef SYM

    const int SM_128_256_1 = 3 * (1 * 256 * LDT * 2 + 128 * LDT * 2);  // 165888
    const int SM_256_128_1 = 3 * (1 * 128 * LDT * 2 + 256 * LDT * 2);  // 165888

    cudaFuncSetAttribute(gemm_t<256,128,1,2>, cudaFuncAttributeMaxDynamicSharedMemorySize, SM_256_128_1);
    cudaFuncSetAttribute(gemm_t<128,256,1,1>, cudaFuncAttributeMaxDynamicSharedMemorySize, SM_128_256_1);
    cudaFuncSetAttribute(gemm_t<256,128,1,0>, cudaFuncAttributeMaxDynamicSharedMemorySize, SM_256_128_1);
    cudaFuncSetAttribute(gemm_pair,           cudaFuncAttributeMaxDynamicSharedMemorySize, SM_256_128_1);

    dim3 tb(32, 8);

    // weight transposes + hidden convert
    conv_t<<<dim3(48, 64, 1), tb>>>(q_down_W, QR_, w1, H_, H_, QR_);
    conv_h<<<(TOK*H_/4 + 255)/256, 256>>>((const float4*)hidden, hid_h, TOK*H_/4);
    conv_t<<<dim3(18, 64, 1), tb>>>(kv_down_W, KVR_+DR_, w1 + (long)QR_*H_, H_, H_, KVR_+DR_);
    conv_t<<<dim3(96, 48, 1), tb>>>(q_up_W, NH_*QD_, qup_h, QR_, QR_, NH_*QD_);
    conv_t<<<dim3(128, 16, 1), tb>>>(kv_up_W, 4096, kvupw_h, KVR_, KVR_, 4096);

    // merged [qlat | kv] = hidden @ [q_down_W | kv_down_W]   (N=2112, fp32 out)
    gemm_t<256,128,1,0><<<dim3(9, 32, 1), 256, SM_256_128_1>>>(
        hid_h, nullptr, 0, H_, w1, 0, H_,
        kvq, 0, 0, W1N, nullptr, W1N, H_, 1.f);

    conv_t<<<dim3(64, 64, 1), tb>>>(out_W, H_, outw_h, NH_*DV_, NH_*DV_, H_);

    // merged rmsnorms -> fp16
    rmsnorm2<<<dim3(TOK, 2), 256>>>(kvq, q_norm_w, kv_norm_w, qlat_h, kvlat_h);

    // qup + kvup in one launch (fp16 out, staged stores)
    gemm_pair<<<384 + 512, 256, SM_256_128_1>>>(
        qlat_h, QR_, qup_h, QR_, qf_h, NH_*QD_, NH_*QD_, QR_, 12, 384,
        kvlat_h, KVR_, kvupw_h, KVR_, kvup_h, 4096, 4096, KVR_, 16);

    // q_states / k_states with RoPE (vectorized half2)
    build_qs2<<<(ZBH * S_ * QD_ / 2) / 256, 256>>>(qf_h, pos, qs_h);
    build_ks2<<<(ZBH * S_ * QD_ / 2) / 256, 256>>>(kvup_h, kvq, pos, ks_h);
    // v^T per (b,h): [dv, s] from fp16 kvup
    conv_t16<<<dim3(4, 64, ZBH), tb>>>(kvup_h + DN_, 4096, (long)S_*4096, 256,
                                       vt_h, S_, (long)DV_*S_, S_, DV_);
    // p = exp(scale*Q@K^T - OFF) -> fp16 at_h (staged stores)
    gemm_t<256,128,1,2><<<dim3(8, 16, ZBH), 256, SM_256_128_1>>>(
        qs_h, nullptr, (long)S_*QD_, QD_, ks_h, (long)S_*QD_, QD_,
        at_h, (long)NH_*S_*S_, (long)S_*S_, S_,
        nullptr, S_, QD_, 0.0721687836487032f);
    // normalize: fp32 attn output + 1/rowsum
    attn_norm<<<ZBH*S_, 256>>>(at_h, attn, invs);
    // pv = p @ Vh scaled by 1/rowsum -> fp16 token-major (staged stores)
    gemm_t<128,256,1,1><<<dim3(1, 8, ZBH), 256, SM_128_256_1>>>(
        at_h, nullptr, (long)S_*S_, S_, vt_h, (long)DV_*S_, S_,
        ao_h, (long)S_*2048, DV_, 2048,
        invs, DV_, S_, 1.f);
    // out = ao_h @ out_W
    gemm_t<256,128,1,0><<<dim3(8, 32, 1), 256, SM_256_128_1>>>(
        ao_h, nullptr, 0, NH_*DV_, outw_h, 0, NH_*DV_,
        out, 0, 0, H_, nullptr, H_, NH_*DV_, 1.f);
}